// round 1
// baseline (speedup 1.0000x reference)
#include <cuda_runtime.h>

#define Nn 50000
#define Ee 800000
#define Dd 128
#define EDd 50
#define Hh 128
#define Gg 256
#define ETot (Ee + Nn)

// ---------------- static device scratch (no runtime allocation) ----------------
__device__ float g_bufA[Nn * Hh];   // h = x @ W (linear output)
__device__ float g_bufB[Nn * Hh];   // aggregation accumulator
__device__ float g_bufC[Nn * Hh];   // layer-1 activated output
__device__ float g_als[Nn];
__device__ float g_ald[Nn];
__device__ float g_ale[2][Ee];      // per-edge attention-edge logits, both layers
__device__ float g_alpha[ETot];     // alpha, then reused as exp(alpha-max)
__device__ int   g_amax[Nn];        // order-preserving int keys for float max
__device__ float g_denom[Nn];
__device__ float g_weae[2][EDd];    // We @ ae, both layers
__device__ float g_alesum[2];       // sum of al_e over real edges (for self-loop mean)
__device__ float g_gsum[Gg];
__device__ float g_gcnt[Gg];

// ---------------- helpers ----------------
__device__ __forceinline__ int f2key(float f) {
    int i = __float_as_int(f);
    return (i >= 0) ? i : (i ^ 0x7fffffff);
}
__device__ __forceinline__ float key2f(int k) {
    return __int_as_float((k >= 0) ? k : (k ^ 0x7fffffff));
}

// ---------------- K0: prep (weae vectors + zero accumulators) ----------------
__global__ void k_prep(const float* __restrict__ We1, const float* __restrict__ ae1,
                       const float* __restrict__ We2, const float* __restrict__ ae2) {
    int t = threadIdx.x;  // 256 threads
    if (t < EDd) {
        float s = 0.f;
        #pragma unroll 8
        for (int k = 0; k < Hh; k++) s += We1[t * Hh + k] * ae1[k];
        g_weae[0][t] = s;
    } else if (t >= 128 && t < 128 + EDd) {
        int j = t - 128;
        float s = 0.f;
        #pragma unroll 8
        for (int k = 0; k < Hh; k++) s += We2[j * Hh + k] * ae2[k];
        g_weae[1][j] = s;
    }
    if (t < 2) g_alesum[t] = 0.f;
    g_gsum[t] = 0.f;
    g_gcnt[t] = 0.f;
}

// ---------------- K2: per-edge al_e for both layers + running sums ----------------
__global__ void k_ale(const float* __restrict__ EA) {
    __shared__ float w1s[EDd], w2s[EDd];
    __shared__ float r1[8], r2[8];
    int t = threadIdx.x;
    if (t < EDd) { w1s[t] = g_weae[0][t]; w2s[t] = g_weae[1][t]; }
    __syncthreads();
    int e = blockIdx.x * blockDim.x + t;
    float s1 = 0.f, s2 = 0.f;
    if (e < Ee) {
        const float* r = EA + (size_t)e * EDd;
        #pragma unroll
        for (int j = 0; j < EDd; j++) {
            float v = __ldg(r + j);
            s1 += v * w1s[j];
            s2 += v * w2s[j];
        }
        g_ale[0][e] = s1;
        g_ale[1][e] = s2;
    }
    // block reduce for edge-mean (self-loop al_e)
    float t1 = s1, t2 = s2;
    #pragma unroll
    for (int o = 16; o; o >>= 1) {
        t1 += __shfl_down_sync(0xffffffffu, t1, o);
        t2 += __shfl_down_sync(0xffffffffu, t2, o);
    }
    int lane = t & 31, wid = t >> 5;
    if (lane == 0) { r1[wid] = t1; r2[wid] = t2; }
    __syncthreads();
    if (t == 0) {
        float a1 = 0.f, a2 = 0.f;
        #pragma unroll
        for (int i = 0; i < 8; i++) { a1 += r1[i]; a2 += r2[i]; }
        atomicAdd(&g_alesum[0], a1);
        atomicAdd(&g_alesum[1], a2);
    }
}

// ---------------- per-layer init: amax keys / denom ----------------
__global__ void k_init_layer() {
    int n = blockIdx.x * blockDim.x + threadIdx.x;
    if (n < Nn) {
        g_amax[n] = 0x80000000;  // minimum key
        g_denom[n] = 0.f;
    }
}

// ---------------- K1: tiled fp32 GEMM  O[n,128] = X[n,128] @ W[128,128] ----------------
__global__ void k_gemm(const float* __restrict__ X, const float* __restrict__ W,
                       float* __restrict__ O, int n) {
    __shared__ __align__(16) float xs[32][72];   // [k][row] padded (16B-aligned rows)
    __shared__ __align__(16) float ws[32][128];  // [k][col]
    int tid = threadIdx.x;           // 256
    int row0 = blockIdx.x * 64;
    int cg = tid & 31;               // column group -> cols 4*cg..4*cg+3
    int ng = tid >> 5;               // warp id -> nodes 8*ng..8*ng+7
    float acc[8][4];
    #pragma unroll
    for (int i = 0; i < 8; i++)
        #pragma unroll
        for (int j = 0; j < 4; j++) acc[i][j] = 0.f;

    for (int kc = 0; kc < 128; kc += 32) {
        #pragma unroll
        for (int i = 0; i < 8; i++) {
            int idx = tid + i * 256;
            int r = idx >> 5, kk = idx & 31;
            int grow = row0 + r;
            xs[kk][r] = (grow < n) ? X[grow * 128 + kc + kk] : 0.f;
        }
        #pragma unroll
        for (int i = 0; i < 16; i++) {
            int idx = tid + i * 256;
            int kk = idx >> 7, col = idx & 127;
            ws[kk][col] = W[(kc + kk) * 128 + col];
        }
        __syncthreads();
        #pragma unroll
        for (int k = 0; k < 32; k++) {
            float4 a0 = *(const float4*)&xs[k][8 * ng];
            float4 a1 = *(const float4*)&xs[k][8 * ng + 4];
            float4 b  = *(const float4*)&ws[k][4 * cg];
            float av[8] = {a0.x, a0.y, a0.z, a0.w, a1.x, a1.y, a1.z, a1.w};
            float bv[4] = {b.x, b.y, b.z, b.w};
            #pragma unroll
            for (int i = 0; i < 8; i++)
                #pragma unroll
                for (int j = 0; j < 4; j++) acc[i][j] += av[i] * bv[j];
        }
        __syncthreads();
    }
    #pragma unroll
    for (int i = 0; i < 8; i++) {
        int grow = row0 + 8 * ng + i;
        if (grow < n)
            *(float4*)&O[grow * 128 + 4 * cg] =
                make_float4(acc[i][0], acc[i][1], acc[i][2], acc[i][3]);
    }
}

// ---------------- K1b: per-node attention dots al_s, al_d ----------------
__global__ void k_attdot(const float* __restrict__ Hm, const float* __restrict__ asrc,
                         const float* __restrict__ adst) {
    int gt = blockIdx.x * blockDim.x + threadIdx.x;
    int w = gt >> 5, lane = gt & 31;
    if (w >= Nn) return;
    const float* hr = Hm + (size_t)w * Hh;
    float s = 0.f, d = 0.f;
    #pragma unroll
    for (int c = lane; c < Hh; c += 32) {
        float hv = hr[c];
        s += hv * __ldg(asrc + c);
        d += hv * __ldg(adst + c);
    }
    #pragma unroll
    for (int o = 16; o; o >>= 1) {
        s += __shfl_down_sync(0xffffffffu, s, o);
        d += __shfl_down_sync(0xffffffffu, d, o);
    }
    if (lane == 0) { g_als[w] = s; g_ald[w] = d; }
}

// ---------------- K3: alpha = leakyrelu(...) + segment max (atomicMax on keys) ----------------
__global__ void k_alpha(const int* __restrict__ src, const int* __restrict__ dst, int layer) {
    int e = blockIdx.x * blockDim.x + threadIdx.x;
    if (e >= ETot) return;
    int s, d;
    float ale;
    if (e < Ee) {
        s = __ldg(src + e);
        d = __ldg(dst + e);
        ale = g_ale[layer][e];
    } else {
        s = d = e - Ee;
        ale = g_alesum[layer] * (1.0f / (float)Ee);
    }
    float a = g_als[s] + g_ald[d] + ale;
    a = (a > 0.f) ? a : 0.2f * a;
    g_alpha[e] = a;
    atomicMax(&g_amax[d], f2key(a));
}

// ---------------- K4: ex = exp(alpha - max), denom += ex ----------------
__global__ void k_exp(const int* __restrict__ dst) {
    int e = blockIdx.x * blockDim.x + threadIdx.x;
    if (e >= ETot) return;
    int d = (e < Ee) ? __ldg(dst + e) : (e - Ee);
    float m = key2f(g_amax[d]);
    float ex = __expf(g_alpha[e] - m);
    g_alpha[e] = ex;
    atomicAdd(&g_denom[d], ex);
}

// ---------------- K5: aggregation  out[dst] += h[src] * coef  (warp per edge) ----------------
__global__ void k_agg(const int* __restrict__ src, const int* __restrict__ dst,
                      const float* __restrict__ Hm) {
    int gt = blockIdx.x * blockDim.x + threadIdx.x;
    int w = gt >> 5, lane = gt & 31;
    if (w >= ETot) return;
    int s, d;
    if (w < Ee) {
        s = __ldg(src + w);
        d = __ldg(dst + w);
    } else {
        s = d = w - Ee;
    }
    float coef = g_alpha[w] / g_denom[d];
    float4 hv = *(const float4*)(Hm + (size_t)s * Hh + lane * 4);
    float4 r;
    r.x = hv.x * coef; r.y = hv.y * coef; r.z = hv.z * coef; r.w = hv.w * coef;
    float* op = g_bufB + (size_t)d * Hh + lane * 4;
    asm volatile("red.relaxed.gpu.global.add.v4.f32 [%0], {%1, %2, %3, %4};"
                 :: "l"(op), "f"(r.x), "f"(r.y), "f"(r.z), "f"(r.w)
                 : "memory");
}

// ---------------- K6: bias + relu ----------------
__global__ void k_bias_relu(const float* __restrict__ bias, const float* __restrict__ in,
                            float* __restrict__ outp) {
    int idx = blockIdx.x * blockDim.x + threadIdx.x;
    if (idx >= Nn * Hh) return;
    float v = in[idx] + __ldg(bias + (idx & (Hh - 1)));
    outp[idx] = (v > 0.f) ? v : 0.f;
}

// ---------------- K7: pooled dot with Wfc, segment sums per graph ----------------
__global__ void k_pool(const float* __restrict__ Hm, const int* __restrict__ batch,
                       const float* __restrict__ wfc) {
    int gt = blockIdx.x * blockDim.x + threadIdx.x;
    int w = gt >> 5, lane = gt & 31;
    if (w >= Nn) return;
    const float4 hv = *(const float4*)(Hm + (size_t)w * Hh + lane * 4);
    const float4 wv = *(const float4*)(wfc + lane * 4);
    float s = hv.x * wv.x + hv.y * wv.y + hv.z * wv.z + hv.w * wv.w;
    #pragma unroll
    for (int o = 16; o; o >>= 1) s += __shfl_down_sync(0xffffffffu, s, o);
    if (lane == 0) {
        int g = __ldg(batch + w);
        atomicAdd(&g_gsum[g], s);
        atomicAdd(&g_gcnt[g], 1.f);
    }
}

// ---------------- K8: finalize output ----------------
__global__ void k_final(float* __restrict__ out, const float* __restrict__ bfc) {
    int g = threadIdx.x;  // 256
    float c = g_gcnt[g];
    out[g] = g_gsum[g] / fmaxf(c, 1.f) + bfc[0];
}

// ---------------- host ----------------
extern "C" void kernel_launch(void* const* d_in, const int* in_sizes, int n_in,
                              void* d_out, int out_size) {
    const float* x    = (const float*)d_in[0];
    const int*   ei   = (const int*)d_in[1];
    const float* ea   = (const float*)d_in[2];
    const int*   batch = (const int*)d_in[3];
    const float* W1  = (const float*)d_in[4];
    const float* as1 = (const float*)d_in[5];
    const float* ad1 = (const float*)d_in[6];
    const float* We1 = (const float*)d_in[7];
    const float* ae1 = (const float*)d_in[8];
    const float* b1  = (const float*)d_in[9];
    const float* W2  = (const float*)d_in[10];
    const float* as2 = (const float*)d_in[11];
    const float* ad2 = (const float*)d_in[12];
    const float* We2 = (const float*)d_in[13];
    const float* ae2 = (const float*)d_in[14];
    const float* b2  = (const float*)d_in[15];
    const float* Wfc = (const float*)d_in[16];
    const float* bfc = (const float*)d_in[17];

    const int* src = ei;
    const int* dst = ei + Ee;

    void *pA_, *pB_, *pC_;
    cudaGetSymbolAddress(&pA_, g_bufA);
    cudaGetSymbolAddress(&pB_, g_bufB);
    cudaGetSymbolAddress(&pC_, g_bufC);
    float* pA = (float*)pA_;
    float* pB = (float*)pB_;
    float* pC = (float*)pC_;

    const int GB_E   = (Ee + 255) / 256;
    const int GB_ET  = (ETot + 255) / 256;
    const int GB_N   = (Nn + 255) / 256;
    const int GB_NW  = (Nn * 32 + 255) / 256;   // warp per node
    const int GB_ETW = ((long long)ETot * 32 + 255) / 256;  // warp per edge
    const int GB_NH  = (Nn * Hh + 255) / 256;
    const int GB_GEMM = (Nn + 63) / 64;

    // prep
    k_prep<<<1, 256>>>(We1, ae1, We2, ae2);
    k_ale<<<GB_E, 256>>>(ea);

    // ---- layer 1 ----
    cudaMemsetAsync(pB, 0, sizeof(float) * Nn * Hh);
    k_init_layer<<<GB_N, 256>>>();
    k_gemm<<<GB_GEMM, 256>>>(x, W1, pA, Nn);
    k_attdot<<<GB_NW, 256>>>(pA, as1, ad1);
    k_alpha<<<GB_ET, 256>>>(src, dst, 0);
    k_exp<<<GB_ET, 256>>>(dst);
    k_agg<<<GB_ETW, 256>>>(src, dst, pA);
    k_bias_relu<<<GB_NH, 256>>>(b1, pB, pC);

    // ---- layer 2 ----
    cudaMemsetAsync(pB, 0, sizeof(float) * Nn * Hh);
    k_init_layer<<<GB_N, 256>>>();
    k_gemm<<<GB_GEMM, 256>>>(pC, W2, pA, Nn);
    k_attdot<<<GB_NW, 256>>>(pA, as2, ad2);
    k_alpha<<<GB_ET, 256>>>(src, dst, 1);
    k_exp<<<GB_ET, 256>>>(dst);
    k_agg<<<GB_ETW, 256>>>(src, dst, pA);
    k_bias_relu<<<GB_NH, 256>>>(b2, pB, pB);

    // ---- pool + fc ----
    k_pool<<<GB_NW, 256>>>(pB, batch, Wfc);
    k_final<<<1, 256>>>((float*)d_out, bfc);
}

// round 2
// speedup vs baseline: 1.5333x; 1.5333x over previous
#include <cuda_runtime.h>

#define Nn 50000
#define Ee 800000
#define Dd 128
#define EDd 50
#define Hh 128
#define Gg 256

#define FULLMASK 0xffffffffu

// ---------------- static device scratch ----------------
__device__ float g_bufA[Nn * Hh];   // h = X @ W
__device__ float g_bufC[Nn * Hh];   // layer-1 activated output
__device__ float g_als[Nn];
__device__ float g_ald[Nn];
__device__ float g_ale[2][Ee];      // per-edge attention-edge logits (orig order)
__device__ float g_alpha[Ee];       // alpha in CSR order
__device__ float g_weae[2][EDd];
__device__ float g_alesum[2];
__device__ float g_gsum[Gg];
__device__ float g_gcnt[Gg];
// CSR
__device__ int   g_cnt[Nn];
__device__ int   g_rp[Nn + 1];
__device__ int   g_wp[Nn];
__device__ int   g_bsum[64];
__device__ int   g_boff[64];
__device__ int   g_csr_src[Ee];
__device__ float g_csr_a0[Ee];
__device__ float g_csr_a1[Ee];

// ---------------- K0: prep ----------------
__global__ void k_prep(const float* __restrict__ We1, const float* __restrict__ ae1,
                       const float* __restrict__ We2, const float* __restrict__ ae2) {
    int t = threadIdx.x;  // 256
    if (t < EDd) {
        float s = 0.f;
        #pragma unroll 8
        for (int k = 0; k < Hh; k++) s += We1[t * Hh + k] * ae1[k];
        g_weae[0][t] = s;
    } else if (t >= 128 && t < 128 + EDd) {
        int j = t - 128;
        float s = 0.f;
        #pragma unroll 8
        for (int k = 0; k < Hh; k++) s += We2[j * Hh + k] * ae2[k];
        g_weae[1][j] = s;
    }
    if (t < 2) g_alesum[t] = 0.f;
    g_gsum[t] = 0.f;
    g_gcnt[t] = 0.f;
}

__global__ void k_cnt_batch(const int* __restrict__ batch) {
    int n = blockIdx.x * blockDim.x + threadIdx.x;
    if (n < Nn) atomicAdd(&g_gcnt[__ldg(batch + n)], 1.f);
}

// ---------------- K_ale: coalesced edge-logit GEMV (both layers) ----------------
// 128 edges / block, staged through smem.
__global__ void k_ale(const float* __restrict__ EA) {
    __shared__ float sh[128 * EDd];       // 25.6 KB
    __shared__ float w1s[EDd], w2s[EDd];
    __shared__ float r1[8], r2[8];
    int t = threadIdx.x;  // 256
    if (t < EDd) { w1s[t] = g_weae[0][t]; w2s[t] = g_weae[1][t]; }

    // coalesced stage of 128*50 floats
    size_t base = (size_t)blockIdx.x * 128 * EDd;
    size_t lim = (size_t)Ee * EDd;
    #pragma unroll
    for (int k = 0; k < 25; k++) {
        size_t gi = base + t + k * 256;
        sh[t + k * 256] = (gi < lim) ? __ldg(EA + gi) : 0.f;
    }
    __syncthreads();

    // 2 threads per edge: half = t&1 covers 25 features
    int el = t >> 1, half = t & 1;
    int e = blockIdx.x * 128 + el;
    const float* row = sh + el * EDd + half * 25;
    const float* w1 = w1s + half * 25;
    const float* w2 = w2s + half * 25;
    float s1 = 0.f, s2 = 0.f;
    #pragma unroll
    for (int j = 0; j < 25; j++) {
        float v = row[j];
        s1 += v * w1[j];
        s2 += v * w2[j];
    }
    float p1 = __shfl_down_sync(FULLMASK, s1, 1);
    float p2 = __shfl_down_sync(FULLMASK, s2, 1);
    float f1 = 0.f, f2 = 0.f;
    if (half == 0 && e < Ee) {
        f1 = s1 + p1;
        f2 = s2 + p2;
        g_ale[0][e] = f1;
        g_ale[1][e] = f2;
    }
    // block reduce for alesum
    #pragma unroll
    for (int o = 16; o; o >>= 1) {
        f1 += __shfl_down_sync(FULLMASK, f1, o);
        f2 += __shfl_down_sync(FULLMASK, f2, o);
    }
    int lane = t & 31, wid = t >> 5;
    if (lane == 0) { r1[wid] = f1; r2[wid] = f2; }
    __syncthreads();
    if (t == 0) {
        float a1 = 0.f, a2 = 0.f;
        #pragma unroll
        for (int i = 0; i < 8; i++) { a1 += r1[i]; a2 += r2[i]; }
        atomicAdd(&g_alesum[0], a1);
        atomicAdd(&g_alesum[1], a2);
    }
}

// ---------------- CSR build ----------------
__global__ void k_count(const int* __restrict__ dst) {
    int e = blockIdx.x * blockDim.x + threadIdx.x;
    if (e < Ee) atomicAdd(&g_cnt[__ldg(dst + e)], 1);
}

// block-wise exclusive scan (1024/block)
__global__ void k_scan1() {
    __shared__ int sh[1024];
    int t = threadIdx.x;
    int i = blockIdx.x * 1024 + t;
    int v = (i < Nn) ? g_cnt[i] : 0;
    sh[t] = v;
    __syncthreads();
    #pragma unroll
    for (int o = 1; o < 1024; o <<= 1) {
        int x = (t >= o) ? sh[t - o] : 0;
        __syncthreads();
        sh[t] += x;
        __syncthreads();
    }
    if (i < Nn) g_rp[i] = sh[t] - v;   // exclusive within block
    if (t == 1023) g_bsum[blockIdx.x] = sh[1023];
}

__global__ void k_scan2(int nblk) {
    __shared__ int sh[64];
    int t = threadIdx.x;  // 64
    int v = (t < nblk) ? g_bsum[t] : 0;
    sh[t] = v;
    __syncthreads();
    #pragma unroll
    for (int o = 1; o < 64; o <<= 1) {
        int x = (t >= o) ? sh[t - o] : 0;
        __syncthreads();
        sh[t] += x;
        __syncthreads();
    }
    g_boff[t] = sh[t] - v;  // exclusive
}

__global__ void k_scan3() {
    int i = blockIdx.x * blockDim.x + threadIdx.x;
    if (i < Nn) {
        int v = g_rp[i] + g_boff[i >> 10];
        g_rp[i] = v;
        g_wp[i] = v;
    }
    if (i == 0) g_rp[Nn] = Ee;
}

__global__ void k_scatter(const int* __restrict__ src, const int* __restrict__ dst) {
    int e = blockIdx.x * blockDim.x + threadIdx.x;
    if (e >= Ee) return;
    int d = __ldg(dst + e);
    int pos = atomicAdd(&g_wp[d], 1);
    g_csr_src[pos] = __ldg(src + e);
    g_csr_a0[pos] = g_ale[0][e];
    g_csr_a1[pos] = g_ale[1][e];
}

// ---------------- GEMM + fused attention-dot epilogue ----------------
__global__ void k_gemm(const float* __restrict__ X, const float* __restrict__ W,
                       float* __restrict__ O,
                       const float* __restrict__ asrc, const float* __restrict__ adst,
                       int n) {
    __shared__ __align__(16) float xs[32][72];
    __shared__ __align__(16) float ws[32][128];
    int tid = threadIdx.x;           // 256
    int row0 = blockIdx.x * 64;
    int cg = tid & 31;               // lane -> cols 4*cg..4*cg+3
    int ng = tid >> 5;               // warp -> nodes 8*ng..8*ng+7
    float acc[8][4];
    #pragma unroll
    for (int i = 0; i < 8; i++)
        #pragma unroll
        for (int j = 0; j < 4; j++) acc[i][j] = 0.f;

    for (int kc = 0; kc < 128; kc += 32) {
        #pragma unroll
        for (int i = 0; i < 8; i++) {
            int idx = tid + i * 256;
            int r = idx >> 5, kk = idx & 31;
            int grow = row0 + r;
            xs[kk][r] = (grow < n) ? X[grow * 128 + kc + kk] : 0.f;
        }
        #pragma unroll
        for (int i = 0; i < 16; i++) {
            int idx = tid + i * 256;
            int kk = idx >> 7, col = idx & 127;
            ws[kk][col] = W[(kc + kk) * 128 + col];
        }
        __syncthreads();
        #pragma unroll
        for (int k = 0; k < 32; k++) {
            float4 a0 = *(const float4*)&xs[k][8 * ng];
            float4 a1 = *(const float4*)&xs[k][8 * ng + 4];
            float4 b  = *(const float4*)&ws[k][4 * cg];
            float av[8] = {a0.x, a0.y, a0.z, a0.w, a1.x, a1.y, a1.z, a1.w};
            float bv[4] = {b.x, b.y, b.z, b.w};
            #pragma unroll
            for (int i = 0; i < 8; i++)
                #pragma unroll
                for (int j = 0; j < 4; j++) acc[i][j] += av[i] * bv[j];
        }
        __syncthreads();
    }
    float4 vs = *(const float4*)(asrc + 4 * cg);
    float4 vd = *(const float4*)(adst + 4 * cg);
    #pragma unroll
    for (int i = 0; i < 8; i++) {
        int grow = row0 + 8 * ng + i;
        float s = acc[i][0] * vs.x + acc[i][1] * vs.y + acc[i][2] * vs.z + acc[i][3] * vs.w;
        float d = acc[i][0] * vd.x + acc[i][1] * vd.y + acc[i][2] * vd.z + acc[i][3] * vd.w;
        #pragma unroll
        for (int o = 16; o; o >>= 1) {
            s += __shfl_down_sync(FULLMASK, s, o);
            d += __shfl_down_sync(FULLMASK, d, o);
        }
        if (grow < n) {
            *(float4*)&O[grow * 128 + 4 * cg] =
                make_float4(acc[i][0], acc[i][1], acc[i][2], acc[i][3]);
            if (cg == 0) { g_als[grow] = s; g_ald[grow] = d; }
        }
    }
}

// ---------------- fused softmax + aggregation (warp per dst node) ----------------
// LAYER 0: writes relu(agg + bias) to outbuf.
// LAYER 1: computes pooled dot with wfc, atomicAdd to g_gsum[batch[n]].
template <int LAYER>
__global__ void k_agg_fused(const float* __restrict__ Hm, const float* __restrict__ bias,
                            float* __restrict__ outbuf,
                            const int* __restrict__ batch, const float* __restrict__ wfc) {
    int gt = blockIdx.x * blockDim.x + threadIdx.x;
    int n = gt >> 5, lane = gt & 31;
    if (n >= Nn) return;
    const float* csr_ale = (LAYER == 0) ? g_csr_a0 : g_csr_a1;
    int beg = g_rp[n], end = g_rp[n + 1];
    int deg = end - beg;
    float aldn = g_ald[n];

    // pass A: alpha + segment max
    float m = -3.4e38f;
    for (int i = lane; i < deg; i += 32) {
        int e = beg + i;
        int s = g_csr_src[e];
        float a = g_als[s] + aldn + csr_ale[e];
        a = (a > 0.f) ? a : 0.2f * a;
        g_alpha[e] = a;
        m = fmaxf(m, a);
    }
    float aself = g_als[n] + aldn + g_alesum[LAYER] * (1.0f / (float)Ee);
    aself = (aself > 0.f) ? aself : 0.2f * aself;
    m = fmaxf(m, aself);
    #pragma unroll
    for (int o = 16; o; o >>= 1) m = fmaxf(m, __shfl_xor_sync(FULLMASK, m, o));

    // pass B: exp, denom, weighted numerator
    float4 acc = make_float4(0.f, 0.f, 0.f, 0.f);
    float dsum = 0.f;
    for (int base = 0; base < deg; base += 32) {
        int i = base + lane;
        float ex = 0.f;
        int s = 0;
        if (i < deg) {
            int e = beg + i;
            s = g_csr_src[e];
            ex = __expf(g_alpha[e] - m);
        }
        dsum += ex;
        int cnt = min(32, deg - base);
        for (int j = 0; j < cnt; j++) {
            float exj = __shfl_sync(FULLMASK, ex, j);
            int sj = __shfl_sync(FULLMASK, s, j);
            const float4 hv = *(const float4*)(Hm + (size_t)sj * Hh + lane * 4);
            acc.x += exj * hv.x;
            acc.y += exj * hv.y;
            acc.z += exj * hv.z;
            acc.w += exj * hv.w;
        }
    }
    // self loop
    float exs = __expf(aself - m);
    const float4 hs = *(const float4*)(Hm + (size_t)n * Hh + lane * 4);
    acc.x += exs * hs.x; acc.y += exs * hs.y; acc.z += exs * hs.z; acc.w += exs * hs.w;
    #pragma unroll
    for (int o = 16; o; o >>= 1) dsum += __shfl_xor_sync(FULLMASK, dsum, o);
    dsum += exs;
    float inv = 1.0f / dsum;

    float4 bv = *(const float4*)(bias + lane * 4);
    float4 ov;
    ov.x = fmaxf(acc.x * inv + bv.x, 0.f);
    ov.y = fmaxf(acc.y * inv + bv.y, 0.f);
    ov.z = fmaxf(acc.z * inv + bv.z, 0.f);
    ov.w = fmaxf(acc.w * inv + bv.w, 0.f);

    if (LAYER == 0) {
        *(float4*)(outbuf + (size_t)n * Hh + lane * 4) = ov;
    } else {
        float4 wv = *(const float4*)(wfc + lane * 4);
        float p = ov.x * wv.x + ov.y * wv.y + ov.z * wv.z + ov.w * wv.w;
        #pragma unroll
        for (int o = 16; o; o >>= 1) p += __shfl_down_sync(FULLMASK, p, o);
        if (lane == 0) atomicAdd(&g_gsum[__ldg(batch + n)], p);
    }
}

// ---------------- finalize ----------------
__global__ void k_final(float* __restrict__ out, const float* __restrict__ bfc) {
    int g = threadIdx.x;  // 256
    float c = g_gcnt[g];
    out[g] = g_gsum[g] / fmaxf(c, 1.f) + bfc[0];
}

// ---------------- host ----------------
extern "C" void kernel_launch(void* const* d_in, const int* in_sizes, int n_in,
                              void* d_out, int out_size) {
    const float* x    = (const float*)d_in[0];
    const int*   ei   = (const int*)d_in[1];
    const float* ea   = (const float*)d_in[2];
    const int*   batch = (const int*)d_in[3];
    const float* W1  = (const float*)d_in[4];
    const float* as1 = (const float*)d_in[5];
    const float* ad1 = (const float*)d_in[6];
    const float* We1 = (const float*)d_in[7];
    const float* ae1 = (const float*)d_in[8];
    const float* b1  = (const float*)d_in[9];
    const float* W2  = (const float*)d_in[10];
    const float* as2 = (const float*)d_in[11];
    const float* ad2 = (const float*)d_in[12];
    const float* We2 = (const float*)d_in[13];
    const float* ae2 = (const float*)d_in[14];
    const float* b2  = (const float*)d_in[15];
    const float* Wfc = (const float*)d_in[16];
    const float* bfc = (const float*)d_in[17];

    const int* src = ei;
    const int* dst = ei + Ee;

    void* pA_; void* pC_; void* pCnt_;
    cudaGetSymbolAddress(&pA_, g_bufA);
    cudaGetSymbolAddress(&pC_, g_bufC);
    cudaGetSymbolAddress(&pCnt_, g_cnt);
    float* pA = (float*)pA_;
    float* pC = (float*)pC_;

    const int GB_E    = (Ee + 255) / 256;
    const int GB_N    = (Nn + 255) / 256;
    const int GB_NW   = (Nn * 32 + 255) / 256;   // warp per node
    const int GB_GEMM = (Nn + 63) / 64;
    const int GB_ALE  = (Ee + 127) / 128;
    const int NSCAN   = (Nn + 1023) / 1024;

    // prep + edge logits + graph counts
    k_prep<<<1, 256>>>(We1, ae1, We2, ae2);
    k_cnt_batch<<<GB_N, 256>>>(batch);
    k_ale<<<GB_ALE, 256>>>(ea);

    // CSR build (by dst)
    cudaMemsetAsync(pCnt_, 0, sizeof(int) * Nn);
    k_count<<<GB_E, 256>>>(dst);
    k_scan1<<<NSCAN, 1024>>>();
    k_scan2<<<1, 64>>>(NSCAN);
    k_scan3<<<GB_N, 256>>>();
    k_scatter<<<GB_E, 256>>>(src, dst);

    // ---- layer 1 ----
    k_gemm<<<GB_GEMM, 256>>>(x, W1, pA, as1, ad1, Nn);
    k_agg_fused<0><<<GB_NW, 256>>>(pA, b1, pC, batch, Wfc);

    // ---- layer 2 ----
    k_gemm<<<GB_GEMM, 256>>>(pC, W2, pA, as2, ad2, Nn);
    k_agg_fused<1><<<GB_NW, 256>>>(pA, b2, nullptr, batch, Wfc);

    // ---- finalize ----
    k_final<<<1, 256>>>((float*)d_out, bfc);
}

// round 3
// speedup vs baseline: 1.7021x; 1.1100x over previous
#include <cuda_runtime.h>

#define Nn 50000
#define Ee 800000
#define Dd 128
#define EDd 50
#define Hh 128
#define Gg 256

#define FULLMASK 0xffffffffu

// ---------------- static device scratch ----------------
__device__ float g_bufA[Nn * Hh];   // h = X @ W
__device__ float g_bufC[Nn * Hh];   // layer-1 activated output
__device__ float g_als[Nn];
__device__ float g_ald[Nn];
__device__ float g_ale[2][Ee];      // per-edge attention-edge logits (orig order)
__device__ float g_alpha[Ee];       // alpha in CSR order (slow path only)
__device__ float g_weae[2][EDd];
__device__ float g_alesum[2];
__device__ float g_gsum[Gg];
__device__ float g_gcnt[Gg];
// CSR
__device__ int   g_cnt[Nn];
__device__ int   g_rp[Nn + 1];
__device__ int   g_wp[Nn];
__device__ int   g_bsum[64];
__device__ int   g_boff[64];
__device__ int   g_csr_src[Ee];
__device__ float g_csr_a0[Ee];
__device__ float g_csr_a1[Ee];

// ---------------- f32x2 helpers ----------------
__device__ __forceinline__ unsigned long long pk2dup(float v) {
    unsigned long long r;
    asm("mov.b64 %0, {%1, %1};" : "=l"(r) : "f"(v));
    return r;
}
__device__ __forceinline__ void upk2(unsigned long long v, float& lo, float& hi) {
    asm("mov.b64 {%0, %1}, %2;" : "=f"(lo), "=f"(hi) : "l"(v));
}
__device__ __forceinline__ unsigned long long ffma2(unsigned long long a,
                                                    unsigned long long b,
                                                    unsigned long long c) {
    unsigned long long d;
    asm("fma.rn.f32x2 %0, %1, %2, %3;" : "=l"(d) : "l"(a), "l"(b), "l"(c));
    return d;
}

// ---------------- K0: prep ----------------
__global__ void k_prep(const float* __restrict__ We1, const float* __restrict__ ae1,
                       const float* __restrict__ We2, const float* __restrict__ ae2) {
    int t = threadIdx.x;  // 256
    if (t < EDd) {
        float s = 0.f;
        #pragma unroll 8
        for (int k = 0; k < Hh; k++) s += We1[t * Hh + k] * ae1[k];
        g_weae[0][t] = s;
    } else if (t >= 128 && t < 128 + EDd) {
        int j = t - 128;
        float s = 0.f;
        #pragma unroll 8
        for (int k = 0; k < Hh; k++) s += We2[j * Hh + k] * ae2[k];
        g_weae[1][j] = s;
    }
    if (t < 2) g_alesum[t] = 0.f;
    g_gsum[t] = 0.f;
    g_gcnt[t] = 0.f;
}

__global__ void k_cnt_batch(const int* __restrict__ batch) {
    int n = blockIdx.x * blockDim.x + threadIdx.x;
    if (n < Nn) atomicAdd(&g_gcnt[__ldg(batch + n)], 1.f);
}

// ---------------- K_ale: coalesced edge-logit GEMV (both layers) ----------------
__global__ void k_ale(const float* __restrict__ EA) {
    __shared__ float sh[128 * EDd];
    __shared__ float w1s[EDd], w2s[EDd];
    __shared__ float r1[8], r2[8];
    int t = threadIdx.x;  // 256
    if (t < EDd) { w1s[t] = g_weae[0][t]; w2s[t] = g_weae[1][t]; }

    size_t base = (size_t)blockIdx.x * 128 * EDd;
    size_t lim = (size_t)Ee * EDd;
    #pragma unroll
    for (int k = 0; k < 25; k++) {
        size_t gi = base + t + k * 256;
        sh[t + k * 256] = (gi < lim) ? __ldg(EA + gi) : 0.f;
    }
    __syncthreads();

    int el = t >> 1, half = t & 1;
    int e = blockIdx.x * 128 + el;
    const float* row = sh + el * EDd + half * 25;
    const float* w1 = w1s + half * 25;
    const float* w2 = w2s + half * 25;
    float s1 = 0.f, s2 = 0.f;
    #pragma unroll
    for (int j = 0; j < 25; j++) {
        float v = row[j];
        s1 += v * w1[j];
        s2 += v * w2[j];
    }
    float p1 = __shfl_down_sync(FULLMASK, s1, 1);
    float p2 = __shfl_down_sync(FULLMASK, s2, 1);
    float f1 = 0.f, f2 = 0.f;
    if (half == 0 && e < Ee) {
        f1 = s1 + p1;
        f2 = s2 + p2;
        g_ale[0][e] = f1;
        g_ale[1][e] = f2;
    }
    #pragma unroll
    for (int o = 16; o; o >>= 1) {
        f1 += __shfl_down_sync(FULLMASK, f1, o);
        f2 += __shfl_down_sync(FULLMASK, f2, o);
    }
    int lane = t & 31, wid = t >> 5;
    if (lane == 0) { r1[wid] = f1; r2[wid] = f2; }
    __syncthreads();
    if (t == 0) {
        float a1 = 0.f, a2 = 0.f;
        #pragma unroll
        for (int i = 0; i < 8; i++) { a1 += r1[i]; a2 += r2[i]; }
        atomicAdd(&g_alesum[0], a1);
        atomicAdd(&g_alesum[1], a2);
    }
}

// ---------------- CSR build ----------------
__global__ void k_count(const int* __restrict__ dst) {
    int e = blockIdx.x * blockDim.x + threadIdx.x;
    if (e < Ee) atomicAdd(&g_cnt[__ldg(dst + e)], 1);
}

__global__ void k_scan1() {
    __shared__ int sh[1024];
    int t = threadIdx.x;
    int i = blockIdx.x * 1024 + t;
    int v = (i < Nn) ? g_cnt[i] : 0;
    sh[t] = v;
    __syncthreads();
    #pragma unroll
    for (int o = 1; o < 1024; o <<= 1) {
        int x = (t >= o) ? sh[t - o] : 0;
        __syncthreads();
        sh[t] += x;
        __syncthreads();
    }
    if (i < Nn) g_rp[i] = sh[t] - v;
    if (t == 1023) g_bsum[blockIdx.x] = sh[1023];
}

__global__ void k_scan2(int nblk) {
    __shared__ int sh[64];
    int t = threadIdx.x;  // 64
    int v = (t < nblk) ? g_bsum[t] : 0;
    sh[t] = v;
    __syncthreads();
    #pragma unroll
    for (int o = 1; o < 64; o <<= 1) {
        int x = (t >= o) ? sh[t - o] : 0;
        __syncthreads();
        sh[t] += x;
        __syncthreads();
    }
    g_boff[t] = sh[t] - v;
}

__global__ void k_scan3() {
    int i = blockIdx.x * blockDim.x + threadIdx.x;
    if (i < Nn) {
        int v = g_rp[i] + g_boff[i >> 10];
        g_rp[i] = v;
        g_wp[i] = v;
    }
    if (i == 0) g_rp[Nn] = Ee;
}

__global__ void k_scatter(const int* __restrict__ src, const int* __restrict__ dst) {
    int e = blockIdx.x * blockDim.x + threadIdx.x;
    if (e >= Ee) return;
    int d = __ldg(dst + e);
    int pos = atomicAdd(&g_wp[d], 1);
    g_csr_src[pos] = __ldg(src + e);
    g_csr_a0[pos] = g_ale[0][e];
    g_csr_a1[pos] = g_ale[1][e];
}

// ---------------- GEMM (f32x2) + fused attention-dot epilogue ----------------
__global__ void __launch_bounds__(256) k_gemm(
        const float* __restrict__ X, const float* __restrict__ W,
        float* __restrict__ O,
        const float* __restrict__ asrc, const float* __restrict__ adst,
        int n) {
    __shared__ __align__(16) float xs[32][72];
    __shared__ __align__(16) float ws[32][128];
    int tid = threadIdx.x;           // 256
    int row0 = blockIdx.x * 64;
    int cg = tid & 31;               // lane -> cols 4*cg..4*cg+3
    int ng = tid >> 5;               // warp -> nodes 8*ng..8*ng+7
    unsigned long long acc2[4][4];   // [row-pair][col], lo=row 2p, hi=row 2p+1
    #pragma unroll
    for (int p = 0; p < 4; p++)
        #pragma unroll
        for (int j = 0; j < 4; j++) acc2[p][j] = 0ull;

    for (int kc = 0; kc < 128; kc += 32) {
        #pragma unroll
        for (int i = 0; i < 8; i++) {
            int idx = tid + i * 256;
            int r = idx >> 5, kk = idx & 31;
            int grow = row0 + r;
            xs[kk][r] = (grow < n) ? X[grow * 128 + kc + kk] : 0.f;
        }
        #pragma unroll
        for (int i = 0; i < 16; i++) {
            int idx = tid + i * 256;
            int kk = idx >> 7, col = idx & 127;
            ws[kk][col] = W[(kc + kk) * 128 + col];
        }
        __syncthreads();
        #pragma unroll
        for (int k = 0; k < 32; k++) {
            const ulonglong2* ap = (const ulonglong2*)&xs[k][8 * ng];
            ulonglong2 a01 = ap[0];
            ulonglong2 a23 = ap[1];
            float4 b = *(const float4*)&ws[k][4 * cg];
            unsigned long long ar[4] = {a01.x, a01.y, a23.x, a23.y};
            unsigned long long bd[4] = {pk2dup(b.x), pk2dup(b.y), pk2dup(b.z), pk2dup(b.w)};
            #pragma unroll
            for (int p = 0; p < 4; p++)
                #pragma unroll
                for (int j = 0; j < 4; j++)
                    acc2[p][j] = ffma2(ar[p], bd[j], acc2[p][j]);
        }
        __syncthreads();
    }
    // unpack
    float acc[8][4];
    #pragma unroll
    for (int p = 0; p < 4; p++)
        #pragma unroll
        for (int j = 0; j < 4; j++)
            upk2(acc2[p][j], acc[2 * p][j], acc[2 * p + 1][j]);

    float4 vs = *(const float4*)(asrc + 4 * cg);
    float4 vd = *(const float4*)(adst + 4 * cg);
    #pragma unroll
    for (int i = 0; i < 8; i++) {
        int grow = row0 + 8 * ng + i;
        float s = acc[i][0] * vs.x + acc[i][1] * vs.y + acc[i][2] * vs.z + acc[i][3] * vs.w;
        float d = acc[i][0] * vd.x + acc[i][1] * vd.y + acc[i][2] * vd.z + acc[i][3] * vd.w;
        #pragma unroll
        for (int o = 16; o; o >>= 1) {
            s += __shfl_down_sync(FULLMASK, s, o);
            d += __shfl_down_sync(FULLMASK, d, o);
        }
        if (grow < n) {
            *(float4*)&O[grow * 128 + 4 * cg] =
                make_float4(acc[i][0], acc[i][1], acc[i][2], acc[i][3]);
            if (cg == 0) { g_als[grow] = s; g_ald[grow] = d; }
        }
    }
}

// ---------------- fused softmax + aggregation (warp per dst node) ----------------
template <int LAYER>
__global__ void k_agg_fused(const float* __restrict__ Hm, const float* __restrict__ bias,
                            float* __restrict__ outbuf,
                            const int* __restrict__ batch, const float* __restrict__ wfc) {
    __shared__ int2 sh[8][32];
    int gt = blockIdx.x * blockDim.x + threadIdx.x;
    int n = gt >> 5, lane = gt & 31;
    int w = threadIdx.x >> 5;
    if (n >= Nn) return;
    const float* csr_ale = (LAYER == 0) ? g_csr_a0 : g_csr_a1;
    int beg = g_rp[n], deg = g_rp[n + 1] - beg;
    float aldn = g_ald[n];
    float aself = g_als[n] + aldn + g_alesum[LAYER] * (1.0f / (float)Ee);
    aself = (aself > 0.f) ? aself : 0.2f * aself;

    unsigned long long acc01 = 0ull, acc23 = 0ull;
    float dsum = 0.f;
    float m;

    if (deg <= 32) {
        // ---- fast path: alpha stays in registers ----
        int e = beg + lane;
        bool v = lane < deg;
        int s = 0;
        float a = -3.4e38f;
        if (v) {
            s = g_csr_src[e];
            a = g_als[s] + aldn + csr_ale[e];
            a = (a > 0.f) ? a : 0.2f * a;
        }
        m = a;
        #pragma unroll
        for (int o = 16; o; o >>= 1) m = fmaxf(m, __shfl_xor_sync(FULLMASK, m, o));
        m = fmaxf(m, aself);
        float ex = v ? __expf(a - m) : 0.f;
        dsum = ex;
        sh[w][lane] = make_int2(s, __float_as_int(ex));
        __syncwarp();
        #pragma unroll 4
        for (int j = 0; j < deg; j++) {
            int2 p = sh[w][j];
            unsigned long long exd = pk2dup(__int_as_float(p.y));
            const ulonglong2 hv = *(const ulonglong2*)(Hm + (size_t)p.x * Hh + lane * 4);
            acc01 = ffma2(exd, hv.x, acc01);
            acc23 = ffma2(exd, hv.y, acc23);
        }
    } else {
        // ---- slow path ----
        m = -3.4e38f;
        for (int i = lane; i < deg; i += 32) {
            int e = beg + i;
            int s = g_csr_src[e];
            float a = g_als[s] + aldn + csr_ale[e];
            a = (a > 0.f) ? a : 0.2f * a;
            g_alpha[e] = a;
            m = fmaxf(m, a);
        }
        #pragma unroll
        for (int o = 16; o; o >>= 1) m = fmaxf(m, __shfl_xor_sync(FULLMASK, m, o));
        m = fmaxf(m, aself);
        for (int base = 0; base < deg; base += 32) {
            int i = base + lane;
            float ex = 0.f;
            int s = 0;
            if (i < deg) {
                int e = beg + i;
                s = g_csr_src[e];
                ex = __expf(g_alpha[e] - m);
            }
            dsum += ex;
            sh[w][lane] = make_int2(s, __float_as_int(ex));
            __syncwarp();
            int cnt = min(32, deg - base);
            #pragma unroll 4
            for (int j = 0; j < cnt; j++) {
                int2 p = sh[w][j];
                unsigned long long exd = pk2dup(__int_as_float(p.y));
                const ulonglong2 hv = *(const ulonglong2*)(Hm + (size_t)p.x * Hh + lane * 4);
                acc01 = ffma2(exd, hv.x, acc01);
                acc23 = ffma2(exd, hv.y, acc23);
            }
            __syncwarp();
        }
    }

    // self loop
    float exs = __expf(aself - m);
    {
        unsigned long long exd = pk2dup(exs);
        const ulonglong2 hv = *(const ulonglong2*)(Hm + (size_t)n * Hh + lane * 4);
        acc01 = ffma2(exd, hv.x, acc01);
        acc23 = ffma2(exd, hv.y, acc23);
    }
    #pragma unroll
    for (int o = 16; o; o >>= 1) dsum += __shfl_xor_sync(FULLMASK, dsum, o);
    dsum += exs;
    float inv = 1.0f / dsum;

    float4 acc;
    upk2(acc01, acc.x, acc.y);
    upk2(acc23, acc.z, acc.w);

    float4 bv = *(const float4*)(bias + lane * 4);
    float4 ov;
    ov.x = fmaxf(acc.x * inv + bv.x, 0.f);
    ov.y = fmaxf(acc.y * inv + bv.y, 0.f);
    ov.z = fmaxf(acc.z * inv + bv.z, 0.f);
    ov.w = fmaxf(acc.w * inv + bv.w, 0.f);

    if (LAYER == 0) {
        *(float4*)(outbuf + (size_t)n * Hh + lane * 4) = ov;
    } else {
        float4 wv = *(const float4*)(wfc + lane * 4);
        float p = ov.x * wv.x + ov.y * wv.y + ov.z * wv.z + ov.w * wv.w;
        #pragma unroll
        for (int o = 16; o; o >>= 1) p += __shfl_down_sync(FULLMASK, p, o);
        if (lane == 0) atomicAdd(&g_gsum[__ldg(batch + n)], p);
    }
}

// ---------------- finalize ----------------
__global__ void k_final(float* __restrict__ out, const float* __restrict__ bfc) {
    int g = threadIdx.x;  // 256
    float c = g_gcnt[g];
    out[g] = g_gsum[g] / fmaxf(c, 1.f) + bfc[0];
}

// ---------------- host ----------------
extern "C" void kernel_launch(void* const* d_in, const int* in_sizes, int n_in,
                              void* d_out, int out_size) {
    const float* x    = (const float*)d_in[0];
    const int*   ei   = (const int*)d_in[1];
    const float* ea   = (const float*)d_in[2];
    const int*   batch = (const int*)d_in[3];
    const float* W1  = (const float*)d_in[4];
    const float* as1 = (const float*)d_in[5];
    const float* ad1 = (const float*)d_in[6];
    const float* We1 = (const float*)d_in[7];
    const float* ae1 = (const float*)d_in[8];
    const float* b1  = (const float*)d_in[9];
    const float* W2  = (const float*)d_in[10];
    const float* as2 = (const float*)d_in[11];
    const float* ad2 = (const float*)d_in[12];
    const float* We2 = (const float*)d_in[13];
    const float* ae2 = (const float*)d_in[14];
    const float* b2  = (const float*)d_in[15];
    const float* Wfc = (const float*)d_in[16];
    const float* bfc = (const float*)d_in[17];

    const int* src = ei;
    const int* dst = ei + Ee;

    void* pA_; void* pC_; void* pCnt_;
    cudaGetSymbolAddress(&pA_, g_bufA);
    cudaGetSymbolAddress(&pC_, g_bufC);
    cudaGetSymbolAddress(&pCnt_, g_cnt);
    float* pA = (float*)pA_;
    float* pC = (float*)pC_;

    // side streams + events for fork/join (created once; no device mem involved)
    static cudaStream_t s2 = nullptr, s3 = nullptr;
    static cudaEvent_t evP = nullptr, evA = nullptr, evG = nullptr;
    if (!s2) {
        cudaStreamCreateWithFlags(&s2, cudaStreamNonBlocking);
        cudaStreamCreateWithFlags(&s3, cudaStreamNonBlocking);
        cudaEventCreateWithFlags(&evP, cudaEventDisableTiming);
        cudaEventCreateWithFlags(&evA, cudaEventDisableTiming);
        cudaEventCreateWithFlags(&evG, cudaEventDisableTiming);
    }

    const int GB_E    = (Ee + 255) / 256;
    const int GB_N    = (Nn + 255) / 256;
    const int GB_NW   = (Nn * 32 + 255) / 256;   // warp per node
    const int GB_GEMM = (Nn + 63) / 64;
    const int GB_ALE  = (Ee + 127) / 128;
    const int NSCAN   = (Nn + 1023) / 1024;

    // stream 0: prep; then fork
    k_prep<<<1, 256>>>(We1, ae1, We2, ae2);
    cudaMemsetAsync(pCnt_, 0, sizeof(int) * Nn);
    cudaEventRecord(evP, 0);

    // s3: edge logits (needs g_weae from prep)
    cudaStreamWaitEvent(s3, evP, 0);
    k_ale<<<GB_ALE, 256, 0, s3>>>(ea);
    cudaEventRecord(evA, s3);

    // s2: layer-1 GEMM (needs only inputs)
    cudaStreamWaitEvent(s2, evP, 0);
    k_gemm<<<GB_GEMM, 256, 0, s2>>>(x, W1, pA, as1, ad1, Nn);
    cudaEventRecord(evG, s2);

    // stream 0: batch counts + CSR count/scan
    k_cnt_batch<<<GB_N, 256>>>(batch);
    k_count<<<GB_E, 256>>>(dst);
    k_scan1<<<NSCAN, 1024>>>();
    k_scan2<<<1, 64>>>(NSCAN);
    k_scan3<<<GB_N, 256>>>();

    // join ale, then scatter
    cudaStreamWaitEvent(0, evA, 0);
    k_scatter<<<GB_E, 256>>>(src, dst);

    // join gemm1, then layer-1 aggregation
    cudaStreamWaitEvent(0, evG, 0);
    k_agg_fused<0><<<GB_NW, 256>>>(pA, b1, pC, batch, Wfc);

    // ---- layer 2 ----
    k_gemm<<<GB_GEMM, 256>>>(pC, W2, pA, as2, ad2, Nn);
    k_agg_fused<1><<<GB_NW, 256>>>(pA, b2, nullptr, batch, Wfc);

    // ---- finalize ----
    k_final<<<1, 256>>>((float*)d_out, bfc);
}

// round 5
// speedup vs baseline: 1.8629x; 1.0945x over previous
#include <cuda_runtime.h>
#include <cuda_fp16.h>

#define Nn 50000
#define Ee 800000
#define Dd 128
#define EDd 50
#define Hh 128
#define Gg 256

#define FULLMASK 0xffffffffu

// ---------------- static device scratch ----------------
__device__ __half g_bufA[Nn * Hh];  // h = X @ W   (fp16 gather matrix)
__device__ float g_bufC[Nn * Hh];   // layer-1 activated output (fp32, GEMM2 input)
__device__ float g_als[Nn];
__device__ float g_ald[Nn];
__device__ float2 g_ale[Ee];        // per-edge logits, both layers packed (orig order)
__device__ float g_alpha[Ee];       // alpha in CSR order (slow path only)
__device__ float g_weae[2][EDd];
__device__ float g_alesum[2];
__device__ float g_gsum[Gg];
// CSR
__device__ int   g_cnt[Nn];
__device__ int   g_rp[Nn + 1];
__device__ int   g_wp[Nn];
__device__ int   g_bsum[64];
__device__ int   g_boff[64];
__device__ int   g_csr_src[Ee];
__device__ float2 g_csr_a[Ee];      // {layer0, layer1} logits in CSR order

// ---------------- f32x2 helpers ----------------
__device__ __forceinline__ unsigned long long pk2dup(float v) {
    unsigned long long r;
    asm("mov.b64 %0, {%1, %1};" : "=l"(r) : "f"(v));
    return r;
}
__device__ __forceinline__ unsigned long long pk2(float lo, float hi) {
    unsigned long long r;
    asm("mov.b64 %0, {%1, %2};" : "=l"(r) : "f"(lo), "f"(hi));
    return r;
}
__device__ __forceinline__ void upk2(unsigned long long v, float& lo, float& hi) {
    asm("mov.b64 {%0, %1}, %2;" : "=f"(lo), "=f"(hi) : "l"(v));
}
__device__ __forceinline__ unsigned long long ffma2(unsigned long long a,
                                                    unsigned long long b,
                                                    unsigned long long c) {
    unsigned long long d;
    asm("fma.rn.f32x2 %0, %1, %2, %3;" : "=l"(d) : "l"(a), "l"(b), "l"(c));
    return d;
}

// ---------------- K0: prep ----------------
__global__ void k_prep(const float* __restrict__ We1, const float* __restrict__ ae1,
                       const float* __restrict__ We2, const float* __restrict__ ae2) {
    int t = threadIdx.x;  // 256
    if (t < EDd) {
        float s = 0.f;
        #pragma unroll 8
        for (int k = 0; k < Hh; k++) s += We1[t * Hh + k] * ae1[k];
        g_weae[0][t] = s;
    } else if (t >= 128 && t < 128 + EDd) {
        int j = t - 128;
        float s = 0.f;
        #pragma unroll 8
        for (int k = 0; k < Hh; k++) s += We2[j * Hh + k] * ae2[k];
        g_weae[1][j] = s;
    }
    if (t < 2) g_alesum[t] = 0.f;
    g_gsum[t] = 0.f;
}

// ---------------- K_ale: coalesced edge-logit GEMV (both layers) ----------------
__global__ void k_ale(const float* __restrict__ EA) {
    __shared__ float sh[128 * EDd];
    __shared__ float w1s[EDd], w2s[EDd];
    __shared__ float r1[8], r2[8];
    int t = threadIdx.x;  // 256
    if (t < EDd) { w1s[t] = g_weae[0][t]; w2s[t] = g_weae[1][t]; }

    size_t base = (size_t)blockIdx.x * 128 * EDd;
    size_t lim = (size_t)Ee * EDd;
    #pragma unroll
    for (int k = 0; k < 25; k++) {
        size_t gi = base + t + k * 256;
        sh[t + k * 256] = (gi < lim) ? __ldg(EA + gi) : 0.f;
    }
    __syncthreads();

    int el = t >> 1, half = t & 1;
    int e = blockIdx.x * 128 + el;
    const float* row = sh + el * EDd + half * 25;
    const float* w1 = w1s + half * 25;
    const float* w2 = w2s + half * 25;
    float s1 = 0.f, s2 = 0.f;
    #pragma unroll
    for (int j = 0; j < 25; j++) {
        float v = row[j];
        s1 += v * w1[j];
        s2 += v * w2[j];
    }
    float p1 = __shfl_down_sync(FULLMASK, s1, 1);
    float p2 = __shfl_down_sync(FULLMASK, s2, 1);
    float f1 = 0.f, f2 = 0.f;
    if (half == 0 && e < Ee) {
        f1 = s1 + p1;
        f2 = s2 + p2;
        g_ale[e] = make_float2(f1, f2);
    }
    #pragma unroll
    for (int o = 16; o; o >>= 1) {
        f1 += __shfl_down_sync(FULLMASK, f1, o);
        f2 += __shfl_down_sync(FULLMASK, f2, o);
    }
    int lane = t & 31, wid = t >> 5;
    if (lane == 0) { r1[wid] = f1; r2[wid] = f2; }
    __syncthreads();
    if (t == 0) {
        float a1 = 0.f, a2 = 0.f;
        #pragma unroll
        for (int i = 0; i < 8; i++) { a1 += r1[i]; a2 += r2[i]; }
        atomicAdd(&g_alesum[0], a1);
        atomicAdd(&g_alesum[1], a2);
    }
}

// ---------------- CSR build ----------------
__global__ void k_count(const int* __restrict__ dst) {
    int e = blockIdx.x * blockDim.x + threadIdx.x;
    if (e < Ee) atomicAdd(&g_cnt[__ldg(dst + e)], 1);
}

__global__ void k_scan1() {
    __shared__ int sh[1024];
    int t = threadIdx.x;
    int i = blockIdx.x * 1024 + t;
    int v = (i < Nn) ? g_cnt[i] : 0;
    sh[t] = v;
    __syncthreads();
    #pragma unroll
    for (int o = 1; o < 1024; o <<= 1) {
        int x = (t >= o) ? sh[t - o] : 0;
        __syncthreads();
        sh[t] += x;
        __syncthreads();
    }
    if (i < Nn) g_rp[i] = sh[t] - v;
    if (t == 1023) g_bsum[blockIdx.x] = sh[1023];
}

__global__ void k_scan2(int nblk) {
    __shared__ int sh[64];
    int t = threadIdx.x;  // 64
    int v = (t < nblk) ? g_bsum[t] : 0;
    sh[t] = v;
    __syncthreads();
    #pragma unroll
    for (int o = 1; o < 64; o <<= 1) {
        int x = (t >= o) ? sh[t - o] : 0;
        __syncthreads();
        sh[t] += x;
        __syncthreads();
    }
    g_boff[t] = sh[t] - v;
}

__global__ void k_scan3() {
    int i = blockIdx.x * blockDim.x + threadIdx.x;
    if (i < Nn) {
        int v = g_rp[i] + g_boff[i >> 10];
        g_rp[i] = v;
        g_wp[i] = v;
    }
    if (i == 0) g_rp[Nn] = Ee;
}

__global__ void k_scatter(const int* __restrict__ src, const int* __restrict__ dst) {
    int e = blockIdx.x * blockDim.x + threadIdx.x;
    if (e >= Ee) return;
    int d = __ldg(dst + e);
    int pos = atomicAdd(&g_wp[d], 1);
    g_csr_src[pos] = __ldg(src + e);
    g_csr_a[pos] = g_ale[e];
}

// ---------------- GEMM (f32x2) + fused attention-dot epilogue, fp16 output ----------------
__global__ void __launch_bounds__(256) k_gemm(
        const float* __restrict__ X, const float* __restrict__ W,
        __half* __restrict__ O,
        const float* __restrict__ asrc, const float* __restrict__ adst,
        int n) {
    __shared__ __align__(16) float xs[32][72];
    __shared__ __align__(16) float ws[32][128];
    int tid = threadIdx.x;           // 256
    int row0 = blockIdx.x * 64;
    int cg = tid & 31;               // lane -> cols 4*cg..4*cg+3
    int ng = tid >> 5;               // warp -> nodes 8*ng..8*ng+7
    unsigned long long acc2[4][4];   // [row-pair][col]
    #pragma unroll
    for (int p = 0; p < 4; p++)
        #pragma unroll
        for (int j = 0; j < 4; j++) acc2[p][j] = 0ull;

    for (int kc = 0; kc < 128; kc += 32) {
        #pragma unroll
        for (int i = 0; i < 8; i++) {
            int idx = tid + i * 256;
            int r = idx >> 5, kk = idx & 31;
            int grow = row0 + r;
            xs[kk][r] = (grow < n) ? X[grow * 128 + kc + kk] : 0.f;
        }
        #pragma unroll
        for (int i = 0; i < 16; i++) {
            int idx = tid + i * 256;
            int kk = idx >> 7, col = idx & 127;
            ws[kk][col] = W[(kc + kk) * 128 + col];
        }
        __syncthreads();
        #pragma unroll
        for (int k = 0; k < 32; k++) {
            const ulonglong2* ap = (const ulonglong2*)&xs[k][8 * ng];
            ulonglong2 a01 = ap[0];
            ulonglong2 a23 = ap[1];
            float4 b = *(const float4*)&ws[k][4 * cg];
            unsigned long long ar[4] = {a01.x, a01.y, a23.x, a23.y};
            unsigned long long bd[4] = {pk2dup(b.x), pk2dup(b.y), pk2dup(b.z), pk2dup(b.w)};
            #pragma unroll
            for (int p = 0; p < 4; p++)
                #pragma unroll
                for (int j = 0; j < 4; j++)
                    acc2[p][j] = ffma2(ar[p], bd[j], acc2[p][j]);
        }
        __syncthreads();
    }
    float acc[8][4];
    #pragma unroll
    for (int p = 0; p < 4; p++)
        #pragma unroll
        for (int j = 0; j < 4; j++)
            upk2(acc2[p][j], acc[2 * p][j], acc[2 * p + 1][j]);

    float4 vs = *(const float4*)(asrc + 4 * cg);
    float4 vd = *(const float4*)(adst + 4 * cg);
    #pragma unroll
    for (int i = 0; i < 8; i++) {
        int grow = row0 + 8 * ng + i;
        float s = acc[i][0] * vs.x + acc[i][1] * vs.y + acc[i][2] * vs.z + acc[i][3] * vs.w;
        float d = acc[i][0] * vd.x + acc[i][1] * vd.y + acc[i][2] * vd.z + acc[i][3] * vd.w;
        #pragma unroll
        for (int o = 16; o; o >>= 1) {
            s += __shfl_down_sync(FULLMASK, s, o);
            d += __shfl_down_sync(FULLMASK, d, o);
        }
        if (grow < n) {
            __half2 h01 = __floats2half2_rn(acc[i][0], acc[i][1]);
            __half2 h23 = __floats2half2_rn(acc[i][2], acc[i][3]);
            uint2 pkd;
            pkd.x = *reinterpret_cast<unsigned*>(&h01);
            pkd.y = *reinterpret_cast<unsigned*>(&h23);
            *(uint2*)&O[grow * 128 + 4 * cg] = pkd;
            if (cg == 0) { g_als[grow] = s; g_ald[grow] = d; }
        }
    }
}

// ---------------- fused softmax + aggregation (warp per dst node) ----------------
__device__ __forceinline__ void gather_fma(const __half* __restrict__ Hm, int srcn, int lane,
                                           float ex, unsigned long long& acc01,
                                           unsigned long long& acc23) {
    uint2 hv = *(const uint2*)(Hm + (size_t)srcn * Hh + lane * 4);
    float2 f01 = __half22float2(*reinterpret_cast<__half2*>(&hv.x));
    float2 f23 = __half22float2(*reinterpret_cast<__half2*>(&hv.y));
    unsigned long long exd = pk2dup(ex);
    acc01 = ffma2(exd, pk2(f01.x, f01.y), acc01);
    acc23 = ffma2(exd, pk2(f23.x, f23.y), acc23);
}

template <int LAYER>
__global__ void k_agg_fused(const __half* __restrict__ Hm, const float* __restrict__ bias,
                            float* __restrict__ outbuf,
                            const int* __restrict__ batch, const float* __restrict__ wfc) {
    __shared__ int2 sh[8][32];
    int gt = blockIdx.x * blockDim.x + threadIdx.x;
    int n = gt >> 5, lane = gt & 31;
    int w = threadIdx.x >> 5;
    if (n >= Nn) return;
    int beg = g_rp[n], deg = g_rp[n + 1] - beg;
    float aldn = g_ald[n];
    float aself = g_als[n] + aldn + g_alesum[LAYER] * (1.0f / (float)Ee);
    aself = (aself > 0.f) ? aself : 0.2f * aself;

    unsigned long long acc01 = 0ull, acc23 = 0ull;
    float dsum = 0.f;
    float m;

    if (deg <= 32) {
        int e = beg + lane;
        bool v = lane < deg;
        int s = 0;
        float a = -3.4e38f;
        if (v) {
            s = g_csr_src[e];
            float2 al = g_csr_a[e];
            a = g_als[s] + aldn + ((LAYER == 0) ? al.x : al.y);
            a = (a > 0.f) ? a : 0.2f * a;
        }
        m = a;
        #pragma unroll
        for (int o = 16; o; o >>= 1) m = fmaxf(m, __shfl_xor_sync(FULLMASK, m, o));
        m = fmaxf(m, aself);
        float ex = v ? __expf(a - m) : 0.f;
        dsum = ex;
        sh[w][lane] = make_int2(s, __float_as_int(ex));
        __syncwarp();
        #pragma unroll 4
        for (int j = 0; j < deg; j++) {
            int2 p = sh[w][j];
            gather_fma(Hm, p.x, lane, __int_as_float(p.y), acc01, acc23);
        }
    } else {
        m = -3.4e38f;
        for (int i = lane; i < deg; i += 32) {
            int e = beg + i;
            int s = g_csr_src[e];
            float2 al = g_csr_a[e];
            float a = g_als[s] + aldn + ((LAYER == 0) ? al.x : al.y);
            a = (a > 0.f) ? a : 0.2f * a;
            g_alpha[e] = a;
            m = fmaxf(m, a);
        }
        #pragma unroll
        for (int o = 16; o; o >>= 1) m = fmaxf(m, __shfl_xor_sync(FULLMASK, m, o));
        m = fmaxf(m, aself);
        for (int base = 0; base < deg; base += 32) {
            int i = base + lane;
            float ex = 0.f;
            int s = 0;
            if (i < deg) {
                int e = beg + i;
                s = g_csr_src[e];
                ex = __expf(g_alpha[e] - m);
            }
            dsum += ex;
            sh[w][lane] = make_int2(s, __float_as_int(ex));
            __syncwarp();
            int cnt = min(32, deg - base);
            #pragma unroll 4
            for (int j = 0; j < cnt; j++) {
                int2 p = sh[w][j];
                gather_fma(Hm, p.x, lane, __int_as_float(p.y), acc01, acc23);
            }
            __syncwarp();
        }
    }

    // self loop
    float exs = __expf(aself - m);
    gather_fma(Hm, n, lane, exs, acc01, acc23);
    #pragma unroll
    for (int o = 16; o; o >>= 1) dsum += __shfl_xor_sync(FULLMASK, dsum, o);
    dsum += exs;
    float inv = 1.0f / dsum;

    float4 acc;
    upk2(acc01, acc.x, acc.y);
    upk2(acc23, acc.z, acc.w);

    float4 bv = *(const float4*)(bias + lane * 4);
    float4 ov;
    ov.x = fmaxf(acc.x * inv + bv.x, 0.f);
    ov.y = fmaxf(acc.y * inv + bv.y, 0.f);
    ov.z = fmaxf(acc.z * inv + bv.z, 0.f);
    ov.w = fmaxf(acc.w * inv + bv.w, 0.f);

    if (LAYER == 0) {
        *(float4*)(outbuf + (size_t)n * Hh + lane * 4) = ov;
    } else {
        float4 wv = *(const float4*)(wfc + lane * 4);
        float p = ov.x * wv.x + ov.y * wv.y + ov.z * wv.z + ov.w * wv.w;
        #pragma unroll
        for (int o = 16; o; o >>= 1) p += __shfl_down_sync(FULLMASK, p, o);
        if (lane == 0) atomicAdd(&g_gsum[__ldg(batch + n)], p);
    }
}

// ---------------- finalize: counts via binary search over sorted batch ----------------
__global__ void k_final(const int* __restrict__ batch, float* __restrict__ out,
                        const float* __restrict__ bfc) {
    int g = threadIdx.x;  // 256
    int lo0 = 0, hi0 = Nn;
    while (lo0 < hi0) { int mid = (lo0 + hi0) >> 1; if (__ldg(batch + mid) < g) lo0 = mid + 1; else hi0 = mid; }
    int lo1 = lo0, hi1 = Nn;
    while (lo1 < hi1) { int mid = (lo1 + hi1) >> 1; if (__ldg(batch + mid) < g + 1) lo1 = mid + 1; else hi1 = mid; }
    float c = (float)(lo1 - lo0);
    out[g] = g_gsum[g] / fmaxf(c, 1.f) + bfc[0];
}

// ---------------- host ----------------
extern "C" void kernel_launch(void* const* d_in, const int* in_sizes, int n_in,
                              void* d_out, int out_size) {
    const float* x    = (const float*)d_in[0];
    const int*   ei   = (const int*)d_in[1];
    const float* ea   = (const float*)d_in[2];
    const int*   batch = (const int*)d_in[3];
    const float* W1  = (const float*)d_in[4];
    const float* as1 = (const float*)d_in[5];
    const float* ad1 = (const float*)d_in[6];
    const float* We1 = (const float*)d_in[7];
    const float* ae1 = (const float*)d_in[8];
    const float* b1  = (const float*)d_in[9];
    const float* W2  = (const float*)d_in[10];
    const float* as2 = (const float*)d_in[11];
    const float* ad2 = (const float*)d_in[12];
    const float* We2 = (const float*)d_in[13];
    const float* ae2 = (const float*)d_in[14];
    const float* b2  = (const float*)d_in[15];
    const float* Wfc = (const float*)d_in[16];
    const float* bfc = (const float*)d_in[17];

    const int* src = ei;
    const int* dst = ei + Ee;

    void* pA_; void* pC_; void* pCnt_;
    cudaGetSymbolAddress(&pA_, g_bufA);
    cudaGetSymbolAddress(&pC_, g_bufC);
    cudaGetSymbolAddress(&pCnt_, g_cnt);
    __half* pA = (__half*)pA_;
    float* pC = (float*)pC_;

    static cudaStream_t s2 = nullptr, s3 = nullptr;
    static cudaEvent_t evRoot = nullptr, evA = nullptr, evG = nullptr;
    if (!s2) {
        cudaStreamCreateWithFlags(&s2, cudaStreamNonBlocking);
        cudaStreamCreateWithFlags(&s3, cudaStreamNonBlocking);
        cudaEventCreateWithFlags(&evRoot, cudaEventDisableTiming);
        cudaEventCreateWithFlags(&evA, cudaEventDisableTiming);
        cudaEventCreateWithFlags(&evG, cudaEventDisableTiming);
    }

    const int GB_E    = (Ee + 255) / 256;
    const int GB_N    = (Nn + 255) / 256;
    const int GB_NW   = (Nn * 32 + 255) / 256;   // warp per node
    const int GB_GEMM = (Nn + 63) / 64;
    const int GB_ALE  = (Ee + 127) / 128;
    const int NSCAN   = (Nn + 1023) / 1024;

    // Root on the capturing stream (stream 0), then legal fork via events.
    cudaMemsetAsync(pCnt_, 0, sizeof(int) * Nn);   // first node, on stream 0
    cudaEventRecord(evRoot, 0);

    // s2: layer-1 GEMM (forked from capture origin)
    cudaStreamWaitEvent(s2, evRoot, 0);
    k_gemm<<<GB_GEMM, 256, 0, s2>>>(x, W1, pA, as1, ad1, Nn);
    cudaEventRecord(evG, s2);

    // s3: prep (weae, gsum zero) -> edge logits
    cudaStreamWaitEvent(s3, evRoot, 0);
    k_prep<<<1, 256, 0, s3>>>(We1, ae1, We2, ae2);
    k_ale<<<GB_ALE, 256, 0, s3>>>(ea);
    cudaEventRecord(evA, s3);

    // stream 0: CSR count + scan (needs only dst)
    k_count<<<GB_E, 256>>>(dst);
    k_scan1<<<NSCAN, 1024>>>();
    k_scan2<<<1, 64>>>(NSCAN);
    k_scan3<<<GB_N, 256>>>();

    // join ale, then scatter
    cudaStreamWaitEvent(0, evA, 0);
    k_scatter<<<GB_E, 256>>>(src, dst);

    // join gemm1, then layer-1 aggregation
    cudaStreamWaitEvent(0, evG, 0);
    k_agg_fused<0><<<GB_NW, 256>>>(pA, b1, pC, batch, Wfc);

    // ---- layer 2 ----
    k_gemm<<<GB_GEMM, 256>>>(pC, W2, pA, as2, ad2, Nn);
    k_agg_fused<1><<<GB_NW, 256>>>(pA, b2, nullptr, batch, Wfc);

    // ---- finalize ----
    k_final<<<1, 256>>>(batch, (float*)d_out, bfc);
}

// round 6
// speedup vs baseline: 2.2961x; 1.2325x over previous
#include <cuda_runtime.h>
#include <cuda_fp16.h>

#define Nn 50000
#define Ee 800000
#define Dd 128
#define EDd 50
#define Hh 128
#define Gg 256

#define FULLMASK 0xffffffffu

// ---------------- static device scratch ----------------
__device__ __half g_bufA[Nn * Hh];  // h = X @ W   (fp16 gather matrix)
__device__ __half g_bufC[Nn * Hh];  // layer-1 activated output (fp16, GEMM2 input)
__device__ float g_als[Nn];
__device__ float g_ald[Nn];
__device__ float2 g_ale[Ee];        // per-edge logits, both layers packed (orig order)
__device__ float g_alpha[Ee];       // alpha in CSR order (slow path only)
__device__ float g_weae[2][EDd];
__device__ float g_alesum[2];
__device__ float g_gsum[Gg];
// CSR
__device__ int   g_cnt[Nn];
__device__ int   g_rp[Nn + 1];
__device__ int   g_wp[Nn];
__device__ int   g_bsum[64];
__device__ int   g_boff[64];
__device__ int2  g_csr_sp[Ee];      // {src, orig edge index}

// ---------------- f32x2 helpers ----------------
__device__ __forceinline__ unsigned long long pk2dup(float v) {
    unsigned long long r;
    asm("mov.b64 %0, {%1, %1};" : "=l"(r) : "f"(v));
    return r;
}
__device__ __forceinline__ unsigned long long pk2(float lo, float hi) {
    unsigned long long r;
    asm("mov.b64 %0, {%1, %2};" : "=l"(r) : "f"(lo), "f"(hi));
    return r;
}
__device__ __forceinline__ void upk2(unsigned long long v, float& lo, float& hi) {
    asm("mov.b64 {%0, %1}, %2;" : "=f"(lo), "=f"(hi) : "l"(v));
}
__device__ __forceinline__ unsigned long long ffma2(unsigned long long a,
                                                    unsigned long long b,
                                                    unsigned long long c) {
    unsigned long long d;
    asm("fma.rn.f32x2 %0, %1, %2, %3;" : "=l"(d) : "l"(a), "l"(b), "l"(c));
    return d;
}

// ---------------- K0: prep ----------------
__global__ void k_prep(const float* __restrict__ We1, const float* __restrict__ ae1,
                       const float* __restrict__ We2, const float* __restrict__ ae2) {
    int t = threadIdx.x;  // 256
    if (t < EDd) {
        float s = 0.f;
        #pragma unroll 8
        for (int k = 0; k < Hh; k++) s += We1[t * Hh + k] * ae1[k];
        g_weae[0][t] = s;
    } else if (t >= 128 && t < 128 + EDd) {
        int j = t - 128;
        float s = 0.f;
        #pragma unroll 8
        for (int k = 0; k < Hh; k++) s += We2[j * Hh + k] * ae2[k];
        g_weae[1][j] = s;
    }
    if (t < 2) g_alesum[t] = 0.f;
    g_gsum[t] = 0.f;
}

// ---------------- K_ale: coalesced edge-logit GEMV (both layers) ----------------
__global__ void k_ale(const float* __restrict__ EA) {
    __shared__ float sh[128 * EDd];
    __shared__ float w1s[EDd], w2s[EDd];
    __shared__ float r1[8], r2[8];
    int t = threadIdx.x;  // 256
    if (t < EDd) { w1s[t] = g_weae[0][t]; w2s[t] = g_weae[1][t]; }

    size_t base = (size_t)blockIdx.x * 128 * EDd;
    size_t lim = (size_t)Ee * EDd;
    #pragma unroll
    for (int k = 0; k < 25; k++) {
        size_t gi = base + t + k * 256;
        sh[t + k * 256] = (gi < lim) ? __ldg(EA + gi) : 0.f;
    }
    __syncthreads();

    int el = t >> 1, half = t & 1;
    int e = blockIdx.x * 128 + el;
    const float* row = sh + el * EDd + half * 25;
    const float* w1 = w1s + half * 25;
    const float* w2 = w2s + half * 25;
    float s1 = 0.f, s2 = 0.f;
    #pragma unroll
    for (int j = 0; j < 25; j++) {
        float v = row[j];
        s1 += v * w1[j];
        s2 += v * w2[j];
    }
    float p1 = __shfl_down_sync(FULLMASK, s1, 1);
    float p2 = __shfl_down_sync(FULLMASK, s2, 1);
    float f1 = 0.f, f2 = 0.f;
    if (half == 0 && e < Ee) {
        f1 = s1 + p1;
        f2 = s2 + p2;
        g_ale[e] = make_float2(f1, f2);
    }
    #pragma unroll
    for (int o = 16; o; o >>= 1) {
        f1 += __shfl_down_sync(FULLMASK, f1, o);
        f2 += __shfl_down_sync(FULLMASK, f2, o);
    }
    int lane = t & 31, wid = t >> 5;
    if (lane == 0) { r1[wid] = f1; r2[wid] = f2; }
    __syncthreads();
    if (t == 0) {
        float a1 = 0.f, a2 = 0.f;
        #pragma unroll
        for (int i = 0; i < 8; i++) { a1 += r1[i]; a2 += r2[i]; }
        atomicAdd(&g_alesum[0], a1);
        atomicAdd(&g_alesum[1], a2);
    }
}

// ---------------- CSR build ----------------
__global__ void k_count(const int* __restrict__ dst) {
    int e = blockIdx.x * blockDim.x + threadIdx.x;
    if (e < Ee) atomicAdd(&g_cnt[__ldg(dst + e)], 1);
}

__global__ void k_scan1() {
    __shared__ int sh[1024];
    int t = threadIdx.x;
    int i = blockIdx.x * 1024 + t;
    int v = (i < Nn) ? g_cnt[i] : 0;
    sh[t] = v;
    __syncthreads();
    #pragma unroll
    for (int o = 1; o < 1024; o <<= 1) {
        int x = (t >= o) ? sh[t - o] : 0;
        __syncthreads();
        sh[t] += x;
        __syncthreads();
    }
    if (i < Nn) g_rp[i] = sh[t] - v;
    if (t == 1023) g_bsum[blockIdx.x] = sh[1023];
}

__global__ void k_scan2(int nblk) {
    __shared__ int sh[64];
    int t = threadIdx.x;  // 64
    int v = (t < nblk) ? g_bsum[t] : 0;
    sh[t] = v;
    __syncthreads();
    #pragma unroll
    for (int o = 1; o < 64; o <<= 1) {
        int x = (t >= o) ? sh[t - o] : 0;
        __syncthreads();
        sh[t] += x;
        __syncthreads();
    }
    g_boff[t] = sh[t] - v;
}

__global__ void k_scan3() {
    int i = blockIdx.x * blockDim.x + threadIdx.x;
    if (i < Nn) {
        int v = g_rp[i] + g_boff[i >> 10];
        g_rp[i] = v;
        g_wp[i] = v;
    }
    if (i == 0) g_rp[Nn] = Ee;
}

__global__ void k_scatter(const int* __restrict__ src, const int* __restrict__ dst) {
    int e = blockIdx.x * blockDim.x + threadIdx.x;
    if (e >= Ee) return;
    int d = __ldg(dst + e);
    int pos = atomicAdd(&g_wp[d], 1);
    g_csr_sp[pos] = make_int2(__ldg(src + e), e);
}

// ---------------- tensor-core GEMM (HMMA m16n8k16) + attention-dot epilogue ----------------
// Block: 256 threads = 8 warps (4 x warp_m, 2 x warp_n). Tile 128x128, K=128 in 2 chunks of 64.
template <typename TA>
__global__ void __launch_bounds__(256) k_gemm_tc(
        const TA* __restrict__ X, const float* __restrict__ W,
        __half* __restrict__ O,
        const float* __restrict__ asrc, const float* __restrict__ adst,
        int n) {
    __shared__ __align__(16) __half as[128][72];   // [row][k]  (pad 8)
    __shared__ __align__(16) __half ws[128][72];   // [col][k]  (W transposed)
    __shared__ float sred[4][128];                 // als/ald partials per warp_n
    __shared__ float sas[128], sad[128];

    int tid = threadIdx.x;
    int lane = tid & 31, wid = tid >> 5;
    int warp_m = wid & 3, warp_n = wid >> 2;
    int row0 = blockIdx.x * 128;

    if (tid < 128) { sas[tid] = asrc[tid]; sad[tid] = adst[tid]; }

    float c[2][8][4];
    #pragma unroll
    for (int mt = 0; mt < 2; mt++)
        #pragma unroll
        for (int nt = 0; nt < 8; nt++)
            #pragma unroll
            for (int j = 0; j < 4; j++) c[mt][nt][j] = 0.f;

    for (int kc = 0; kc < 128; kc += 64) {
        // ---- stage A (convert to fp16 if needed) ----
        if constexpr (sizeof(TA) == 4) {
            #pragma unroll
            for (int i = 0; i < 8; i++) {
                int linear = tid + i * 256;              // 2048 float4
                int r = linear >> 4, c4 = (linear & 15) * 4;
                int gr = row0 + r; if (gr >= n) gr = n - 1;
                float4 v = *(const float4*)&X[(size_t)gr * 128 + kc + c4];
                __half2 h01 = __floats2half2_rn(v.x, v.y);
                __half2 h23 = __floats2half2_rn(v.z, v.w);
                uint2 pkd;
                pkd.x = *reinterpret_cast<unsigned*>(&h01);
                pkd.y = *reinterpret_cast<unsigned*>(&h23);
                *(uint2*)&as[r][c4] = pkd;
            }
        } else {
            #pragma unroll
            for (int i = 0; i < 4; i++) {
                int linear = tid + i * 256;              // 1024 uint4
                int r = linear >> 3, c8 = (linear & 7) * 8;
                int gr = row0 + r; if (gr >= n) gr = n - 1;
                uint4 v = *(const uint4*)&X[(size_t)gr * 128 + kc + c8];
                *(uint4*)&as[r][c8] = v;
            }
        }
        // ---- stage W transposed: ws[n][k] = W[kc+k][n] ----
        #pragma unroll
        for (int i = 0; i < 8; i++) {
            int linear = tid + i * 256;                  // 2048 float4
            int k = linear >> 5, n4 = (linear & 31) * 4;
            float4 v = *(const float4*)&W[(size_t)(kc + k) * 128 + n4];
            ws[n4 + 0][k] = __float2half(v.x);
            ws[n4 + 1][k] = __float2half(v.y);
            ws[n4 + 2][k] = __float2half(v.z);
            ws[n4 + 3][k] = __float2half(v.w);
        }
        __syncthreads();

        #pragma unroll
        for (int ks = 0; ks < 4; ks++) {
            int k0 = ks * 16;
            int ar = warp_m * 32 + (lane >> 2);
            int ak = k0 + 2 * (lane & 3);
            unsigned a[2][4];
            #pragma unroll
            for (int mt = 0; mt < 2; mt++) {
                a[mt][0] = *(const unsigned*)&as[ar + mt * 16][ak];
                a[mt][1] = *(const unsigned*)&as[ar + mt * 16 + 8][ak];
                a[mt][2] = *(const unsigned*)&as[ar + mt * 16][ak + 8];
                a[mt][3] = *(const unsigned*)&as[ar + mt * 16 + 8][ak + 8];
            }
            #pragma unroll
            for (int nt = 0; nt < 8; nt++) {
                int bn = warp_n * 64 + nt * 8 + (lane >> 2);
                unsigned b0 = *(const unsigned*)&ws[bn][ak];
                unsigned b1 = *(const unsigned*)&ws[bn][ak + 8];
                #pragma unroll
                for (int mt = 0; mt < 2; mt++) {
                    asm volatile(
                        "mma.sync.aligned.m16n8k16.row.col.f32.f16.f16.f32 "
                        "{%0,%1,%2,%3}, {%4,%5,%6,%7}, {%8,%9}, {%0,%1,%2,%3};"
                        : "+f"(c[mt][nt][0]), "+f"(c[mt][nt][1]),
                          "+f"(c[mt][nt][2]), "+f"(c[mt][nt][3])
                        : "r"(a[mt][0]), "r"(a[mt][1]), "r"(a[mt][2]), "r"(a[mt][3]),
                          "r"(b0), "r"(b1));
                }
            }
        }
        __syncthreads();
    }

    // ---- epilogue: store h (fp16) + attention dots ----
    float prs[2][2] = {{0.f, 0.f}, {0.f, 0.f}};   // [mt][row r / r+8] src-dot
    float prd[2][2] = {{0.f, 0.f}, {0.f, 0.f}};
    #pragma unroll
    for (int mt = 0; mt < 2; mt++) {
        int grow = row0 + warp_m * 32 + mt * 16 + (lane >> 2);
        #pragma unroll
        for (int nt = 0; nt < 8; nt++) {
            int gcol = warp_n * 64 + nt * 8 + 2 * (lane & 3);
            float s0 = sas[gcol], s1 = sas[gcol + 1];
            float d0 = sad[gcol], d1 = sad[gcol + 1];
            prs[mt][0] += c[mt][nt][0] * s0 + c[mt][nt][1] * s1;
            prd[mt][0] += c[mt][nt][0] * d0 + c[mt][nt][1] * d1;
            prs[mt][1] += c[mt][nt][2] * s0 + c[mt][nt][3] * s1;
            prd[mt][1] += c[mt][nt][2] * d0 + c[mt][nt][3] * d1;
            if (grow < n) {
                __half2 h = __floats2half2_rn(c[mt][nt][0], c[mt][nt][1]);
                *(unsigned*)&O[(size_t)grow * 128 + gcol] = *reinterpret_cast<unsigned*>(&h);
            }
            if (grow + 8 < n) {
                __half2 h = __floats2half2_rn(c[mt][nt][2], c[mt][nt][3]);
                *(unsigned*)&O[(size_t)(grow + 8) * 128 + gcol] = *reinterpret_cast<unsigned*>(&h);
            }
        }
        // reduce over the 4 lanes sharing a row
        #pragma unroll
        for (int half = 0; half < 2; half++) {
            prs[mt][half] += __shfl_down_sync(FULLMASK, prs[mt][half], 1);
            prs[mt][half] += __shfl_down_sync(FULLMASK, prs[mt][half], 2);
            prd[mt][half] += __shfl_down_sync(FULLMASK, prd[mt][half], 1);
            prd[mt][half] += __shfl_down_sync(FULLMASK, prd[mt][half], 2);
        }
        if ((lane & 3) == 0) {
            int r = warp_m * 32 + mt * 16 + (lane >> 2);
            sred[warp_n][r]     = prs[mt][0];
            sred[warp_n][r + 8] = prs[mt][1];
            sred[2 + warp_n][r]     = prd[mt][0];
            sred[2 + warp_n][r + 8] = prd[mt][1];
        }
    }
    __syncthreads();
    if (tid < 128) {
        int grow = row0 + tid;
        if (grow < n) {
            g_als[grow] = sred[0][tid] + sred[1][tid];
            g_ald[grow] = sred[2][tid] + sred[3][tid];
        }
    }
}

// ---------------- fused softmax + aggregation (warp per dst node) ----------------
__device__ __forceinline__ void gather_fma(const __half* __restrict__ Hm, int srcn, int lane,
                                           float ex, unsigned long long& acc01,
                                           unsigned long long& acc23) {
    uint2 hv = *(const uint2*)(Hm + (size_t)srcn * Hh + lane * 4);
    float2 f01 = __half22float2(*reinterpret_cast<__half2*>(&hv.x));
    float2 f23 = __half22float2(*reinterpret_cast<__half2*>(&hv.y));
    unsigned long long exd = pk2dup(ex);
    acc01 = ffma2(exd, pk2(f01.x, f01.y), acc01);
    acc23 = ffma2(exd, pk2(f23.x, f23.y), acc23);
}

template <int LAYER>
__global__ void k_agg_fused(const __half* __restrict__ Hm, const float* __restrict__ bias,
                            __half* __restrict__ outbuf,
                            const int* __restrict__ batch, const float* __restrict__ wfc) {
    __shared__ int2 sh[8][32];
    int gt = blockIdx.x * blockDim.x + threadIdx.x;
    int n = gt >> 5, lane = gt & 31;
    int w = threadIdx.x >> 5;
    if (n >= Nn) return;
    int beg = g_rp[n], deg = g_rp[n + 1] - beg;
    float aldn = g_ald[n];
    float aself = g_als[n] + aldn + g_alesum[LAYER] * (1.0f / (float)Ee);
    aself = (aself > 0.f) ? aself : 0.2f * aself;

    unsigned long long acc01 = 0ull, acc23 = 0ull;
    float dsum = 0.f;
    float m;

    if (deg <= 32) {
        int e = beg + lane;
        bool v = lane < deg;
        int s = 0;
        float a = -3.4e38f;
        if (v) {
            int2 sp = g_csr_sp[e];
            s = sp.x;
            float2 al = g_ale[sp.y];
            a = g_als[s] + aldn + ((LAYER == 0) ? al.x : al.y);
            a = (a > 0.f) ? a : 0.2f * a;
        }
        m = a;
        #pragma unroll
        for (int o = 16; o; o >>= 1) m = fmaxf(m, __shfl_xor_sync(FULLMASK, m, o));
        m = fmaxf(m, aself);
        float ex = v ? __expf(a - m) : 0.f;
        dsum = ex;
        sh[w][lane] = make_int2(s, __float_as_int(ex));
        __syncwarp();
        #pragma unroll 4
        for (int j = 0; j < deg; j++) {
            int2 p = sh[w][j];
            gather_fma(Hm, p.x, lane, __int_as_float(p.y), acc01, acc23);
        }
    } else {
        m = -3.4e38f;
        for (int i = lane; i < deg; i += 32) {
            int e = beg + i;
            int2 sp = g_csr_sp[e];
            float2 al = g_ale[sp.y];
            float a = g_als[sp.x] + aldn + ((LAYER == 0) ? al.x : al.y);
            a = (a > 0.f) ? a : 0.2f * a;
            g_alpha[e] = a;
            m = fmaxf(m, a);
        }
        #pragma unroll
        for (int o = 16; o; o >>= 1) m = fmaxf(m, __shfl_xor_sync(FULLMASK, m, o));
        m = fmaxf(m, aself);
        for (int base = 0; base < deg; base += 32) {
            int i = base + lane;
            float ex = 0.f;
            int s = 0;
            if (i < deg) {
                int e = beg + i;
                s = g_csr_sp[e].x;
                ex = __expf(g_alpha[e] - m);
            }
            dsum += ex;
            sh[w][lane] = make_int2(s, __float_as_int(ex));
            __syncwarp();
            int cnt = min(32, deg - base);
            #pragma unroll 4
            for (int j = 0; j < cnt; j++) {
                int2 p = sh[w][j];
                gather_fma(Hm, p.x, lane, __int_as_float(p.y), acc01, acc23);
            }
            __syncwarp();
        }
    }

    // self loop
    float exs = __expf(aself - m);
    gather_fma(Hm, n, lane, exs, acc01, acc23);
    #pragma unroll
    for (int o = 16; o; o >>= 1) dsum += __shfl_xor_sync(FULLMASK, dsum, o);
    dsum += exs;
    float inv = 1.0f / dsum;

    float4 acc;
    upk2(acc01, acc.x, acc.y);
    upk2(acc23, acc.z, acc.w);

    float4 bv = *(const float4*)(bias + lane * 4);
    float4 ov;
    ov.x = fmaxf(acc.x * inv + bv.x, 0.f);
    ov.y = fmaxf(acc.y * inv + bv.y, 0.f);
    ov.z = fmaxf(acc.z * inv + bv.z, 0.f);
    ov.w = fmaxf(acc.w * inv + bv.w, 0.f);

    if (LAYER == 0) {
        __half2 o01 = __floats2half2_rn(ov.x, ov.y);
        __half2 o23 = __floats2half2_rn(ov.z, ov.w);
        uint2 pkd;
        pkd.x = *reinterpret_cast<unsigned*>(&o01);
        pkd.y = *reinterpret_cast<unsigned*>(&o23);
        *(uint2*)(outbuf + (size_t)n * Hh + lane * 4) = pkd;
    } else {
        float4 wv = *(const float4*)(wfc + lane * 4);
        float p = ov.x * wv.x + ov.y * wv.y + ov.z * wv.z + ov.w * wv.w;
        #pragma unroll
        for (int o = 16; o; o >>= 1) p += __shfl_down_sync(FULLMASK, p, o);
        if (lane == 0) atomicAdd(&g_gsum[__ldg(batch + n)], p);
    }
}

// ---------------- finalize: counts via binary search over sorted batch ----------------
__global__ void k_final(const int* __restrict__ batch, float* __restrict__ out,
                        const float* __restrict__ bfc) {
    int g = threadIdx.x;  // 256
    int lo0 = 0, hi0 = Nn;
    while (lo0 < hi0) { int mid = (lo0 + hi0) >> 1; if (__ldg(batch + mid) < g) lo0 = mid + 1; else hi0 = mid; }
    int lo1 = lo0, hi1 = Nn;
    while (lo1 < hi1) { int mid = (lo1 + hi1) >> 1; if (__ldg(batch + mid) < g + 1) lo1 = mid + 1; else hi1 = mid; }
    float c = (float)(lo1 - lo0);
    out[g] = g_gsum[g] / fmaxf(c, 1.f) + bfc[0];
}

// ---------------- host ----------------
extern "C" void kernel_launch(void* const* d_in, const int* in_sizes, int n_in,
                              void* d_out, int out_size) {
    const float* x    = (const float*)d_in[0];
    const int*   ei   = (const int*)d_in[1];
    const float* ea   = (const float*)d_in[2];
    const int*   batch = (const int*)d_in[3];
    const float* W1  = (const float*)d_in[4];
    const float* as1 = (const float*)d_in[5];
    const float* ad1 = (const float*)d_in[6];
    const float* We1 = (const float*)d_in[7];
    const float* ae1 = (const float*)d_in[8];
    const float* b1  = (const float*)d_in[9];
    const float* W2  = (const float*)d_in[10];
    const float* as2 = (const float*)d_in[11];
    const float* ad2 = (const float*)d_in[12];
    const float* We2 = (const float*)d_in[13];
    const float* ae2 = (const float*)d_in[14];
    const float* b2  = (const float*)d_in[15];
    const float* Wfc = (const float*)d_in[16];
    const float* bfc = (const float*)d_in[17];

    const int* src = ei;
    const int* dst = ei + Ee;

    void* pA_; void* pC_; void* pCnt_;
    cudaGetSymbolAddress(&pA_, g_bufA);
    cudaGetSymbolAddress(&pC_, g_bufC);
    cudaGetSymbolAddress(&pCnt_, g_cnt);
    __half* pA = (__half*)pA_;
    __half* pC = (__half*)pC_;

    static cudaStream_t s2 = nullptr, s3 = nullptr;
    static cudaEvent_t evRoot = nullptr, evA = nullptr, evG = nullptr;
    if (!s2) {
        cudaStreamCreateWithFlags(&s2, cudaStreamNonBlocking);
        cudaStreamCreateWithFlags(&s3, cudaStreamNonBlocking);
        cudaEventCreateWithFlags(&evRoot, cudaEventDisableTiming);
        cudaEventCreateWithFlags(&evA, cudaEventDisableTiming);
        cudaEventCreateWithFlags(&evG, cudaEventDisableTiming);
    }

    const int GB_E    = (Ee + 255) / 256;
    const int GB_N    = (Nn + 255) / 256;
    const int GB_NW   = (Nn * 32 + 255) / 256;   // warp per node
    const int GB_TC   = (Nn + 127) / 128;
    const int GB_ALE  = (Ee + 127) / 128;
    const int NSCAN   = (Nn + 1023) / 1024;

    // Root on the capturing stream, then legal fork via events.
    cudaMemsetAsync(pCnt_, 0, sizeof(int) * Nn);
    cudaEventRecord(evRoot, 0);

    // s2: layer-1 GEMM (tensor cores)
    cudaStreamWaitEvent(s2, evRoot, 0);
    k_gemm_tc<float><<<GB_TC, 256, 0, s2>>>(x, W1, pA, as1, ad1, Nn);
    cudaEventRecord(evG, s2);

    // s3: prep -> edge logits
    cudaStreamWaitEvent(s3, evRoot, 0);
    k_prep<<<1, 256, 0, s3>>>(We1, ae1, We2, ae2);
    k_ale<<<GB_ALE, 256, 0, s3>>>(ea);
    cudaEventRecord(evA, s3);

    // stream 0: CSR count + scan + scatter (no ale dependency anymore)
    k_count<<<GB_E, 256>>>(dst);
    k_scan1<<<NSCAN, 1024>>>();
    k_scan2<<<1, 64>>>(NSCAN);
    k_scan3<<<GB_N, 256>>>();
    k_scatter<<<GB_E, 256>>>(src, dst);

    // join gemm1 + ale, then layer-1 aggregation
    cudaStreamWaitEvent(0, evG, 0);
    cudaStreamWaitEvent(0, evA, 0);
    k_agg_fused<0><<<GB_NW, 256>>>(pA, b1, pC, batch, Wfc);

    // ---- layer 2 ----
    k_gemm_tc<__half><<<GB_TC, 256>>>(pC, W2, pA, as2, ad2, Nn);
    k_agg_fused<1><<<GB_NW, 256>>>(pA, b2, nullptr, batch, Wfc);

    // ---- finalize ----
    k_final<<<1, 256>>>(batch, (float*)d_out, bfc);
}